// round 9
// baseline (speedup 1.0000x reference)
#include <cuda_runtime.h>
#include <cuda_fp16.h>
#include <cuda_bf16.h>

#define N_NODES 50000
#define N_EDGES 800000
#define D 64
#define BN_EPS 1e-5f

#define SCAN_BS 1024
#define NB1 ((N_NODES + SCAN_BS - 1) / SCAN_BS)   // 49

#define FILL_BLOCKS 782    // ceil(200000/256)
#define GEMM_TILES 391     // ceil(50000/128)

// Scratch (device globals; no allocations allowed).
// INVARIANT: g_cnt is all-zero at kernel_launch entry (zero-init at load;
// scan1_kernel re-zeroes it after use within every call).
__device__ uint2  g_t16[N_NODES * 16];     // t' fp16 (row = 64 halves)
__device__ float4 g_h[N_NODES * (D/4)];    // layer output (fp32)
__device__ float  g_dinv[N_NODES];
__device__ int    g_cnt[N_NODES];
__device__ int    g_off[N_NODES + 1];
__device__ int    g_fill[N_NODES];
__device__ int    g_blk[NB1];
__device__ unsigned short g_csr[N_EDGES];  // source node per CSR slot (fits u16)

__device__ __forceinline__ float2 h2_to_f2(unsigned u) {
    __half2 h = *reinterpret_cast<__half2*>(&u);
    return __half22float2(h);
}
__device__ __forceinline__ unsigned smem_u32(const void* p) {
    return (unsigned)__cvta_generic_to_shared(p);
}

// ---------------------------------------------------------------------------
// hist: in-degree histogram (4 edges / thread).
// ---------------------------------------------------------------------------
__global__ void hist_kernel(const int* __restrict__ coli) {
    int idx = blockIdx.x * blockDim.x + threadIdx.x;   // int4 index
    if (idx < N_EDGES / 4) {
        int4 c = ((const int4*)coli)[idx];
        atomicAdd(&g_cnt[c.x], 1);
        atomicAdd(&g_cnt[c.y], 1);
        atomicAdd(&g_cnt[c.z], 1);
        atomicAdd(&g_cnt[c.w], 1);
    }
}

// ---------------------------------------------------------------------------
// scan1: block partials + local offsets; also dinv and cnt re-zero.
// ---------------------------------------------------------------------------
__global__ __launch_bounds__(256) void scan1_kernel() {
    __shared__ int sh[8];
    int tid = threadIdx.x;
    int lane = tid & 31;
    int wid = tid >> 5;
    int base = blockIdx.x * SCAN_BS + tid * 4;

    int c[4];
    #pragma unroll
    for (int i = 0; i < 4; i++)
        c[i] = (base + i < N_NODES) ? g_cnt[base + i] : 0;
    int tot = c[0] + c[1] + c[2] + c[3];

    int v = tot;
    #pragma unroll
    for (int o = 1; o < 32; o <<= 1) {
        int n = __shfl_up_sync(0xFFFFFFFFu, v, o);
        if (lane >= o) v += n;
    }
    if (lane == 31) sh[wid] = v;
    __syncthreads();
    if (tid < 8) {
        int w = sh[tid];
        #pragma unroll
        for (int o = 1; o < 8; o <<= 1) {
            int n = __shfl_up_sync(0xFFu, w, o, 8);
            if (tid >= o) w += n;
        }
        sh[tid] = w;
    }
    __syncthreads();
    int incl = v + ((wid > 0) ? sh[wid - 1] : 0);
    int run = incl - tot;
    if (tid == 255) g_blk[blockIdx.x] = incl;
    #pragma unroll
    for (int i = 0; i < 4; i++) {
        if (base + i < N_NODES) {
            g_off[base + i] = run;
            g_dinv[base + i] = rsqrtf((float)(c[i] + 1));   // +1 self loop
            g_cnt[base + i] = 0;                            // restore invariant
        }
        run += c[i];
    }
}

// scan3: add cross-block prefix; set fill cursors.
__global__ __launch_bounds__(256) void scan3_kernel() {
    __shared__ int pref;
    int tid = threadIdx.x;
    if (tid == 0) pref = 0;
    __syncthreads();
    int chunk = (blockIdx.x * 256) >> 10;
    if (tid < chunk) atomicAdd(&pref, g_blk[tid]);   // chunk <= 48 < 256
    __syncthreads();

    int i = blockIdx.x * 256 + tid;
    if (i < N_NODES) {
        int off = g_off[i] + pref;
        g_off[i] = off;
        g_fill[i] = off;
        if (i == 0) g_off[N_NODES] = N_EDGES;
    }
}

// ---------------------------------------------------------------------------
// GEMM tile body (HMMA): t' = (in @ W) * dinv, fp16 out to g_t16.
// 128-node tile, 256 threads; warp = 16 rows x 64 cols, mma.m16n8k16.
// ---------------------------------------------------------------------------
#define APAD 72

__device__ __forceinline__ void gemm_tile(int bid, const float* in,
                                          const float* W) {
    __shared__ __half sA[128 * APAD];
    __shared__ __half sB[64 * APAD];

    int tid = threadIdx.x;
    int node0 = bid * 128;

    #pragma unroll
    for (int i = 0; i < 8; i++) {
        int g = tid + 256 * i;
        int k = g >> 5;
        int n2 = g & 31;
        float2 w = ((const float2*)W)[k * 32 + n2];
        *(__half2*)&sB[k * APAD + n2 * 2] = __floats2half2_rn(w.x, w.y);
    }
    #pragma unroll
    for (int i = 0; i < 8; i++) {
        int g = tid + 256 * i;
        int r = g >> 4;
        int c4 = g & 15;
        int node = node0 + r;
        float4 v = make_float4(0.f, 0.f, 0.f, 0.f);
        if (node < N_NODES) {
            if (in) v = ((const float4*)in)[node * 16 + c4];
            else    v = ((const float4*)g_h)[node * 16 + c4];
        }
        __half2* dst = (__half2*)&sA[r * APAD + c4 * 4];
        dst[0] = __floats2half2_rn(v.x, v.y);
        dst[1] = __floats2half2_rn(v.z, v.w);
    }
    __syncthreads();

    int warp = tid >> 5;
    int lane = tid & 31;

    float acc[8][4];
    #pragma unroll
    for (int nc = 0; nc < 8; nc++)
        #pragma unroll
        for (int i = 0; i < 4; i++) acc[nc][i] = 0.f;

    #pragma unroll
    for (int kc = 0; kc < 4; kc++) {
        unsigned a0, a1, a2, a3;
        {
            unsigned addr = smem_u32(
                &sA[(warp * 16 + (lane & 15)) * APAD + kc * 16 + (lane >> 4) * 8]);
            asm volatile("ldmatrix.sync.aligned.m8n8.x4.shared.b16 {%0,%1,%2,%3}, [%4];"
                         : "=r"(a0), "=r"(a1), "=r"(a2), "=r"(a3) : "r"(addr));
        }
        #pragma unroll
        for (int nc = 0; nc < 8; nc++) {
            unsigned b0, b1;
            unsigned addr = smem_u32(&sB[(kc * 16 + (lane & 15)) * APAD + nc * 8]);
            asm volatile("ldmatrix.sync.aligned.m8n8.x2.trans.shared.b16 {%0,%1}, [%2];"
                         : "=r"(b0), "=r"(b1) : "r"(addr));
            asm volatile(
                "mma.sync.aligned.m16n8k16.row.col.f32.f16.f16.f32 "
                "{%0,%1,%2,%3}, {%4,%5,%6,%7}, {%8,%9}, {%0,%1,%2,%3};"
                : "+f"(acc[nc][0]), "+f"(acc[nc][1]), "+f"(acc[nc][2]), "+f"(acc[nc][3])
                : "r"(a0), "r"(a1), "r"(a2), "r"(a3), "r"(b0), "r"(b1));
        }
    }

    int r0 = warp * 16 + (lane >> 2);
    int c0 = lane & 3;
    int node_a = node0 + r0;
    int node_b = node0 + r0 + 8;
    float dva = (node_a < N_NODES) ? g_dinv[node_a] : 0.f;
    float dvb = (node_b < N_NODES) ? g_dinv[node_b] : 0.f;
    __half2* T2 = (__half2*)g_t16;

    #pragma unroll
    for (int nc = 0; nc < 8; nc++) {
        int h2i = nc * 4 + c0;
        if (node_a < N_NODES)
            T2[node_a * 32 + h2i] = __floats2half2_rn(acc[nc][0] * dva, acc[nc][1] * dva);
        if (node_b < N_NODES)
            T2[node_b * 32 + h2i] = __floats2half2_rn(acc[nc][2] * dvb, acc[nc][3] * dvb);
    }
}

// ---------------------------------------------------------------------------
// K4 (fat): CSR fill (blocks [0, FILL_BLOCKS)) + scaled layer-0 GEMM.
// Fill is L2-atomic bound; gemm0 (tensor/smem bound) hides inside it.
// ---------------------------------------------------------------------------
__global__ __launch_bounds__(256) void k4_fill_gemm0(const int* __restrict__ rowi,
                                                     const int* __restrict__ coli,
                                                     const float* __restrict__ x,
                                                     const float* __restrict__ W0) {
    if (blockIdx.x < FILL_BLOCKS) {
        int idx = blockIdx.x * 256 + threadIdx.x;
        if (idx < N_EDGES / 4) {
            int4 r = ((const int4*)rowi)[idx];
            int4 c = ((const int4*)coli)[idx];
            int p0 = atomicAdd(&g_fill[c.x], 1);
            int p1 = atomicAdd(&g_fill[c.y], 1);
            int p2 = atomicAdd(&g_fill[c.z], 1);
            int p3 = atomicAdd(&g_fill[c.w], 1);
            g_csr[p0] = (unsigned short)r.x;
            g_csr[p1] = (unsigned short)r.y;
            g_csr[p2] = (unsigned short)r.z;
            g_csr[p3] = (unsigned short)r.w;
        }
    } else {
        gemm_tile(blockIdx.x - FILL_BLOCKS, x, W0);
    }
}

// ---------------------------------------------------------------------------
// Standalone GEMM (layers 1,2).
// ---------------------------------------------------------------------------
__global__ __launch_bounds__(256) void gemm_kernel(const float* __restrict__ W) {
    gemm_tile(blockIdx.x, nullptr, W);
}

// ---------------------------------------------------------------------------
// Aggregate (pull-mode, fp16 gather via L2, fp32 accumulate) + fused BN/ReLU
// (+ final linear head when last).  8 threads per node, 8 feats each (16B).
// ---------------------------------------------------------------------------
__global__ __launch_bounds__(256) void aggregate_kernel(
        const float* __restrict__ b,
        const float* __restrict__ gamma,
        const float* __restrict__ beta,
        const float* __restrict__ mean,
        const float* __restrict__ var,
        const float* __restrict__ lin_w,
        const float* __restrict__ lin_b,
        float* __restrict__ out,
        int last) {
    int t = blockIdx.x * blockDim.x + threadIdx.x;
    int node = t >> 3;
    int sub = t & 7;
    if (node >= N_NODES) return;

    const uint4* T = (const uint4*)g_t16;

    int s = g_off[node];
    int e = g_off[node + 1];

    float2 a0, a1, a2, a3;
    {
        uint4 v = __ldcg(&T[node * 8 + sub]);
        a0 = h2_to_f2(v.x); a1 = h2_to_f2(v.y);
        a2 = h2_to_f2(v.z); a3 = h2_to_f2(v.w);
    }

    int j = s;
    for (; j + 4 <= e; j += 4) {
        int n0 = g_csr[j + 0];
        int n1 = g_csr[j + 1];
        int n2 = g_csr[j + 2];
        int n3 = g_csr[j + 3];
        uint4 v0 = __ldcg(&T[n0 * 8 + sub]);
        uint4 v1 = __ldcg(&T[n1 * 8 + sub]);
        uint4 v2 = __ldcg(&T[n2 * 8 + sub]);
        uint4 v3 = __ldcg(&T[n3 * 8 + sub]);
        float2 f;
        f = h2_to_f2(v0.x); a0.x += f.x; a0.y += f.y;
        f = h2_to_f2(v0.y); a1.x += f.x; a1.y += f.y;
        f = h2_to_f2(v0.z); a2.x += f.x; a2.y += f.y;
        f = h2_to_f2(v0.w); a3.x += f.x; a3.y += f.y;
        f = h2_to_f2(v1.x); a0.x += f.x; a0.y += f.y;
        f = h2_to_f2(v1.y); a1.x += f.x; a1.y += f.y;
        f = h2_to_f2(v1.z); a2.x += f.x; a2.y += f.y;
        f = h2_to_f2(v1.w); a3.x += f.x; a3.y += f.y;
        f = h2_to_f2(v2.x); a0.x += f.x; a0.y += f.y;
        f = h2_to_f2(v2.y); a1.x += f.x; a1.y += f.y;
        f = h2_to_f2(v2.z); a2.x += f.x; a2.y += f.y;
        f = h2_to_f2(v2.w); a3.x += f.x; a3.y += f.y;
        f = h2_to_f2(v3.x); a0.x += f.x; a0.y += f.y;
        f = h2_to_f2(v3.y); a1.x += f.x; a1.y += f.y;
        f = h2_to_f2(v3.z); a2.x += f.x; a2.y += f.y;
        f = h2_to_f2(v3.w); a3.x += f.x; a3.y += f.y;
    }
    for (; j < e; j++) {
        int n = g_csr[j];
        uint4 v = __ldcg(&T[n * 8 + sub]);
        float2 f;
        f = h2_to_f2(v.x); a0.x += f.x; a0.y += f.y;
        f = h2_to_f2(v.y); a1.x += f.x; a1.y += f.y;
        f = h2_to_f2(v.z); a2.x += f.x; a2.y += f.y;
        f = h2_to_f2(v.w); a3.x += f.x; a3.y += f.y;
    }

    float dv = g_dinv[node];
    float4 acc0 = make_float4(a0.x, a0.y, a1.x, a1.y);
    float4 acc1 = make_float4(a2.x, a2.y, a3.x, a3.y);

    float4 h0, h1;
    {
        float4 bb = ((const float4*)b)[sub * 2 + 0];
        float4 gm = ((const float4*)gamma)[sub * 2 + 0];
        float4 bt = ((const float4*)beta)[sub * 2 + 0];
        float4 mn = ((const float4*)mean)[sub * 2 + 0];
        float4 vr = ((const float4*)var)[sub * 2 + 0];
        h0.x = fmaxf(0.f, (acc0.x * dv + bb.x - mn.x) * rsqrtf(vr.x + BN_EPS) * gm.x + bt.x);
        h0.y = fmaxf(0.f, (acc0.y * dv + bb.y - mn.y) * rsqrtf(vr.y + BN_EPS) * gm.y + bt.y);
        h0.z = fmaxf(0.f, (acc0.z * dv + bb.z - mn.z) * rsqrtf(vr.z + BN_EPS) * gm.z + bt.z);
        h0.w = fmaxf(0.f, (acc0.w * dv + bb.w - mn.w) * rsqrtf(vr.w + BN_EPS) * gm.w + bt.w);
    }
    {
        float4 bb = ((const float4*)b)[sub * 2 + 1];
        float4 gm = ((const float4*)gamma)[sub * 2 + 1];
        float4 bt = ((const float4*)beta)[sub * 2 + 1];
        float4 mn = ((const float4*)mean)[sub * 2 + 1];
        float4 vr = ((const float4*)var)[sub * 2 + 1];
        h1.x = fmaxf(0.f, (acc1.x * dv + bb.x - mn.x) * rsqrtf(vr.x + BN_EPS) * gm.x + bt.x);
        h1.y = fmaxf(0.f, (acc1.y * dv + bb.y - mn.y) * rsqrtf(vr.y + BN_EPS) * gm.y + bt.y);
        h1.z = fmaxf(0.f, (acc1.z * dv + bb.z - mn.z) * rsqrtf(vr.z + BN_EPS) * gm.z + bt.z);
        h1.w = fmaxf(0.f, (acc1.w * dv + bb.w - mn.w) * rsqrtf(vr.w + BN_EPS) * gm.w + bt.w);
    }

    if (!last) {
        ((float4*)g_h)[node * 16 + sub * 2 + 0] = h0;
        ((float4*)g_h)[node * 16 + sub * 2 + 1] = h1;
    } else {
        float4 w0 = ((const float4*)lin_w)[sub * 2 + 0];
        float4 w1 = ((const float4*)lin_w)[sub * 2 + 1];
        float dot = h0.x * w0.x + h0.y * w0.y + h0.z * w0.z + h0.w * w0.w
                  + h1.x * w1.x + h1.y * w1.y + h1.z * w1.z + h1.w * w1.w;
        #pragma unroll
        for (int o = 4; o; o >>= 1)
            dot += __shfl_down_sync(0xFFFFFFFFu, dot, o, 8);
        if (sub == 0) out[node] = dot + lin_b[0];
    }
}

// ---------------------------------------------------------------------------
extern "C" void kernel_launch(void* const* d_in, const int* in_sizes, int n_in,
                              void* d_out, int out_size) {
    const float* x        = (const float*)d_in[0];
    const int*   ei       = (const int*)  d_in[1];   // [2, E]
    const float* Ws       = (const float*)d_in[2];   // [3, 64, 64]
    const float* bs       = (const float*)d_in[3];
    const float* gammas   = (const float*)d_in[4];
    const float* betas    = (const float*)d_in[5];
    const float* means    = (const float*)d_in[6];
    const float* variances= (const float*)d_in[7];
    const float* lin_w    = (const float*)d_in[8];
    const float* lin_b    = (const float*)d_in[9];

    const int* rowi = ei;
    const int* coli = ei + N_EDGES;

    const int agg_blocks = (N_NODES * 8 + 255) / 256;

    hist_kernel<<<(N_EDGES / 4 + 255) / 256, 256>>>(coli);
    scan1_kernel<<<NB1, 256>>>();
    scan3_kernel<<<(N_NODES + 255) / 256, 256>>>();
    // K4: CSR fill (L2-atomic bound) + scaled layer-0 GEMM (tensor bound)
    k4_fill_gemm0<<<FILL_BLOCKS + GEMM_TILES, 256>>>(rowi, coli, x, Ws);

    for (int l = 0; l < 3; l++) {
        if (l > 0)
            gemm_kernel<<<GEMM_TILES, 256>>>(Ws + l * D * D);
        aggregate_kernel<<<agg_blocks, 256>>>(bs + l * D, gammas + l * D,
                                              betas + l * D, means + l * D,
                                              variances + l * D,
                                              lin_w, lin_b, (float*)d_out,
                                              (l == 2) ? 1 : 0);
    }
}

// round 10
// speedup vs baseline: 1.3973x; 1.3973x over previous
#include <cuda_runtime.h>
#include <cuda_fp16.h>
#include <cuda_bf16.h>

#define N_NODES 50000
#define N_EDGES 800000
#define D 64
#define BN_EPS 1e-5f

#define SCAN_BS 1024
#define NB1 ((N_NODES + SCAN_BS - 1) / SCAN_BS)   // 49

#define HIST_BLOCKS 782    // ceil(200000/256)
#define GEMM_TILES 391     // ceil(50000/128)

// Scratch (device globals; no allocations allowed).
// INVARIANT: g_cnt is all-zero at kernel_launch entry (zero-init at load;
// scan1_kernel re-zeroes it after use within every call).
__device__ uint2  g_t16[N_NODES * 16];     // t' fp16 (row = 64 halves)
__device__ float4 g_h[N_NODES * (D/4)];    // layer output (fp32)
__device__ float  g_dinv[N_NODES];
__device__ int    g_cnt[N_NODES];
__device__ int    g_off[N_NODES + 1];
__device__ int    g_fill[N_NODES];
__device__ int    g_blk[NB1];
__device__ unsigned short g_csr[N_EDGES];  // source node per CSR slot (fits u16)

__device__ __forceinline__ float2 h2_to_f2(unsigned u) {
    __half2 h = *reinterpret_cast<__half2*>(&u);
    return __half22float2(h);
}
__device__ __forceinline__ unsigned smem_u32(const void* p) {
    return (unsigned)__cvta_generic_to_shared(p);
}

// ---------------------------------------------------------------------------
// GEMM tile body (HMMA): u = in @ W [* dinv], fp16 out to g_t16.
// 128-node tile, 256 threads; warp = 16 rows x 64 cols, mma.m16n8k16.
// ---------------------------------------------------------------------------
#define APAD 72

__device__ __forceinline__ void gemm_tile(int bid, const float* in,
                                          const float* W, bool scale) {
    __shared__ __half sA[128 * APAD];
    __shared__ __half sB[64 * APAD];

    int tid = threadIdx.x;
    int node0 = bid * 128;

    #pragma unroll
    for (int i = 0; i < 8; i++) {
        int g = tid + 256 * i;
        int k = g >> 5;
        int n2 = g & 31;
        float2 w = ((const float2*)W)[k * 32 + n2];
        *(__half2*)&sB[k * APAD + n2 * 2] = __floats2half2_rn(w.x, w.y);
    }
    #pragma unroll
    for (int i = 0; i < 8; i++) {
        int g = tid + 256 * i;
        int r = g >> 4;
        int c4 = g & 15;
        int node = node0 + r;
        float4 v = make_float4(0.f, 0.f, 0.f, 0.f);
        if (node < N_NODES) {
            if (in) v = ((const float4*)in)[node * 16 + c4];
            else    v = ((const float4*)g_h)[node * 16 + c4];
        }
        __half2* dst = (__half2*)&sA[r * APAD + c4 * 4];
        dst[0] = __floats2half2_rn(v.x, v.y);
        dst[1] = __floats2half2_rn(v.z, v.w);
    }
    __syncthreads();

    int warp = tid >> 5;
    int lane = tid & 31;

    float acc[8][4];
    #pragma unroll
    for (int nc = 0; nc < 8; nc++)
        #pragma unroll
        for (int i = 0; i < 4; i++) acc[nc][i] = 0.f;

    #pragma unroll
    for (int kc = 0; kc < 4; kc++) {
        unsigned a0, a1, a2, a3;
        {
            unsigned addr = smem_u32(
                &sA[(warp * 16 + (lane & 15)) * APAD + kc * 16 + (lane >> 4) * 8]);
            asm volatile("ldmatrix.sync.aligned.m8n8.x4.shared.b16 {%0,%1,%2,%3}, [%4];"
                         : "=r"(a0), "=r"(a1), "=r"(a2), "=r"(a3) : "r"(addr));
        }
        #pragma unroll
        for (int nc = 0; nc < 8; nc++) {
            unsigned b0, b1;
            unsigned addr = smem_u32(&sB[(kc * 16 + (lane & 15)) * APAD + nc * 8]);
            asm volatile("ldmatrix.sync.aligned.m8n8.x2.trans.shared.b16 {%0,%1}, [%2];"
                         : "=r"(b0), "=r"(b1) : "r"(addr));
            asm volatile(
                "mma.sync.aligned.m16n8k16.row.col.f32.f16.f16.f32 "
                "{%0,%1,%2,%3}, {%4,%5,%6,%7}, {%8,%9}, {%0,%1,%2,%3};"
                : "+f"(acc[nc][0]), "+f"(acc[nc][1]), "+f"(acc[nc][2]), "+f"(acc[nc][3])
                : "r"(a0), "r"(a1), "r"(a2), "r"(a3), "r"(b0), "r"(b1));
        }
    }

    int r0 = warp * 16 + (lane >> 2);
    int c0 = lane & 3;
    int node_a = node0 + r0;
    int node_b = node0 + r0 + 8;
    float dva = 1.f, dvb = 1.f;
    if (scale) {
        dva = (node_a < N_NODES) ? g_dinv[node_a] : 0.f;
        dvb = (node_b < N_NODES) ? g_dinv[node_b] : 0.f;
    }
    __half2* T2 = (__half2*)g_t16;

    #pragma unroll
    for (int nc = 0; nc < 8; nc++) {
        int h2i = nc * 4 + c0;
        if (node_a < N_NODES)
            T2[node_a * 32 + h2i] = __floats2half2_rn(acc[nc][0] * dva, acc[nc][1] * dva);
        if (node_b < N_NODES)
            T2[node_b * 32 + h2i] = __floats2half2_rn(acc[nc][2] * dvb, acc[nc][3] * dvb);
    }
}

// ---------------------------------------------------------------------------
// K1 (fat): hist (blocks [0, HIST_BLOCKS)) + UNSCALED layer-0 GEMM.
// (both ~equal duration; overlap verified safe in R8)
// ---------------------------------------------------------------------------
__global__ __launch_bounds__(256) void k1_hist_gemm0(const int* __restrict__ coli,
                                                     const float* __restrict__ x,
                                                     const float* __restrict__ W0) {
    if (blockIdx.x < HIST_BLOCKS) {
        int idx = blockIdx.x * 256 + threadIdx.x;
        if (idx < N_EDGES / 4) {
            int4 c = ((const int4*)coli)[idx];
            atomicAdd(&g_cnt[c.x], 1);
            atomicAdd(&g_cnt[c.y], 1);
            atomicAdd(&g_cnt[c.z], 1);
            atomicAdd(&g_cnt[c.w], 1);
        }
    } else {
        gemm_tile(blockIdx.x - HIST_BLOCKS, x, W0, false);
    }
}

// ---------------------------------------------------------------------------
// scan1: block partials + local offsets; also dinv and cnt re-zero.
// ---------------------------------------------------------------------------
__global__ __launch_bounds__(256) void scan1_kernel() {
    __shared__ int sh[8];
    int tid = threadIdx.x;
    int lane = tid & 31;
    int wid = tid >> 5;
    int base = blockIdx.x * SCAN_BS + tid * 4;

    int c[4];
    #pragma unroll
    for (int i = 0; i < 4; i++)
        c[i] = (base + i < N_NODES) ? g_cnt[base + i] : 0;
    int tot = c[0] + c[1] + c[2] + c[3];

    int v = tot;
    #pragma unroll
    for (int o = 1; o < 32; o <<= 1) {
        int n = __shfl_up_sync(0xFFFFFFFFu, v, o);
        if (lane >= o) v += n;
    }
    if (lane == 31) sh[wid] = v;
    __syncthreads();
    if (tid < 8) {
        int w = sh[tid];
        #pragma unroll
        for (int o = 1; o < 8; o <<= 1) {
            int n = __shfl_up_sync(0xFFu, w, o, 8);
            if (tid >= o) w += n;
        }
        sh[tid] = w;
    }
    __syncthreads();
    int incl = v + ((wid > 0) ? sh[wid - 1] : 0);
    int run = incl - tot;
    if (tid == 255) g_blk[blockIdx.x] = incl;
    #pragma unroll
    for (int i = 0; i < 4; i++) {
        if (base + i < N_NODES) {
            g_off[base + i] = run;
            g_dinv[base + i] = rsqrtf((float)(c[i] + 1));   // +1 self loop
            g_cnt[base + i] = 0;                            // restore invariant
        }
        run += c[i];
    }
}

// scan3: add cross-block prefix; set fill cursors.
__global__ __launch_bounds__(256) void scan3_kernel() {
    __shared__ int pref;
    int tid = threadIdx.x;
    if (tid == 0) pref = 0;
    __syncthreads();
    int chunk = (blockIdx.x * 256) >> 10;
    if (tid < chunk) atomicAdd(&pref, g_blk[tid]);   // chunk <= 48 < 256
    __syncthreads();

    int i = blockIdx.x * 256 + tid;
    if (i < N_NODES) {
        int off = g_off[i] + pref;
        g_off[i] = off;
        g_fill[i] = off;
        if (i == 0) g_off[N_NODES] = N_EDGES;
    }
}

// ---------------------------------------------------------------------------
// fill: CSR fill (standalone; L2-atomic bound, leave it alone).
// ---------------------------------------------------------------------------
__global__ void fill_kernel(const int* __restrict__ rowi,
                            const int* __restrict__ coli) {
    int idx = blockIdx.x * blockDim.x + threadIdx.x;   // int4 index
    if (idx < N_EDGES / 4) {
        int4 r = ((const int4*)rowi)[idx];
        int4 c = ((const int4*)coli)[idx];
        int p0 = atomicAdd(&g_fill[c.x], 1);
        int p1 = atomicAdd(&g_fill[c.y], 1);
        int p2 = atomicAdd(&g_fill[c.z], 1);
        int p3 = atomicAdd(&g_fill[c.w], 1);
        g_csr[p0] = (unsigned short)r.x;
        g_csr[p1] = (unsigned short)r.y;
        g_csr[p2] = (unsigned short)r.z;
        g_csr[p3] = (unsigned short)r.w;
    }
}

// ---------------------------------------------------------------------------
// Standalone GEMM (layers 1,2): scaled.
// ---------------------------------------------------------------------------
__global__ __launch_bounds__(256) void gemm_kernel(const float* __restrict__ W) {
    gemm_tile(blockIdx.x, nullptr, W, true);
}

// ---------------------------------------------------------------------------
// Aggregate (pull-mode, fp16 gather via L2, fp32 accumulate) + fused BN/ReLU
// (+ final linear head when last).  8 threads per node, 8 feats each (16B).
// scale_nbr != 0 (layer 0): g_t16 holds UNSCALED u; multiply each gathered
// row (and the self row) by dinv of its source node.
// ---------------------------------------------------------------------------
__global__ __launch_bounds__(256) void aggregate_kernel(
        const float* __restrict__ b,
        const float* __restrict__ gamma,
        const float* __restrict__ beta,
        const float* __restrict__ mean,
        const float* __restrict__ var,
        const float* __restrict__ lin_w,
        const float* __restrict__ lin_b,
        float* __restrict__ out,
        int last, int scale_nbr) {
    int t = blockIdx.x * blockDim.x + threadIdx.x;
    int node = t >> 3;
    int sub = t & 7;
    if (node >= N_NODES) return;

    const uint4* T = (const uint4*)g_t16;

    int s = g_off[node];
    int e = g_off[node + 1];
    float dv = g_dinv[node];

    float2 a0, a1, a2, a3;
    {
        uint4 v = __ldcg(&T[node * 8 + sub]);
        float sv = scale_nbr ? dv : 1.f;
        float2 f;
        f = h2_to_f2(v.x); a0 = make_float2(f.x * sv, f.y * sv);
        f = h2_to_f2(v.y); a1 = make_float2(f.x * sv, f.y * sv);
        f = h2_to_f2(v.z); a2 = make_float2(f.x * sv, f.y * sv);
        f = h2_to_f2(v.w); a3 = make_float2(f.x * sv, f.y * sv);
    }

    int j = s;
    if (scale_nbr) {
        for (; j + 2 <= e; j += 2) {
            int n0 = g_csr[j + 0];
            int n1 = g_csr[j + 1];
            uint4 v0 = __ldcg(&T[n0 * 8 + sub]);
            uint4 v1 = __ldcg(&T[n1 * 8 + sub]);
            float d0 = g_dinv[n0];
            float d1 = g_dinv[n1];
            float2 f;
            f = h2_to_f2(v0.x); a0.x += f.x * d0; a0.y += f.y * d0;
            f = h2_to_f2(v0.y); a1.x += f.x * d0; a1.y += f.y * d0;
            f = h2_to_f2(v0.z); a2.x += f.x * d0; a2.y += f.y * d0;
            f = h2_to_f2(v0.w); a3.x += f.x * d0; a3.y += f.y * d0;
            f = h2_to_f2(v1.x); a0.x += f.x * d1; a0.y += f.y * d1;
            f = h2_to_f2(v1.y); a1.x += f.x * d1; a1.y += f.y * d1;
            f = h2_to_f2(v1.z); a2.x += f.x * d1; a2.y += f.y * d1;
            f = h2_to_f2(v1.w); a3.x += f.x * d1; a3.y += f.y * d1;
        }
        for (; j < e; j++) {
            int n = g_csr[j];
            uint4 v = __ldcg(&T[n * 8 + sub]);
            float dn = g_dinv[n];
            float2 f;
            f = h2_to_f2(v.x); a0.x += f.x * dn; a0.y += f.y * dn;
            f = h2_to_f2(v.y); a1.x += f.x * dn; a1.y += f.y * dn;
            f = h2_to_f2(v.z); a2.x += f.x * dn; a2.y += f.y * dn;
            f = h2_to_f2(v.w); a3.x += f.x * dn; a3.y += f.y * dn;
        }
    } else {
        for (; j + 4 <= e; j += 4) {
            int n0 = g_csr[j + 0];
            int n1 = g_csr[j + 1];
            int n2 = g_csr[j + 2];
            int n3 = g_csr[j + 3];
            uint4 v0 = __ldcg(&T[n0 * 8 + sub]);
            uint4 v1 = __ldcg(&T[n1 * 8 + sub]);
            uint4 v2 = __ldcg(&T[n2 * 8 + sub]);
            uint4 v3 = __ldcg(&T[n3 * 8 + sub]);
            float2 f;
            f = h2_to_f2(v0.x); a0.x += f.x; a0.y += f.y;
            f = h2_to_f2(v0.y); a1.x += f.x; a1.y += f.y;
            f = h2_to_f2(v0.z); a2.x += f.x; a2.y += f.y;
            f = h2_to_f2(v0.w); a3.x += f.x; a3.y += f.y;
            f = h2_to_f2(v1.x); a0.x += f.x; a0.y += f.y;
            f = h2_to_f2(v1.y); a1.x += f.x; a1.y += f.y;
            f = h2_to_f2(v1.z); a2.x += f.x; a2.y += f.y;
            f = h2_to_f2(v1.w); a3.x += f.x; a3.y += f.y;
            f = h2_to_f2(v2.x); a0.x += f.x; a0.y += f.y;
            f = h2_to_f2(v2.y); a1.x += f.x; a1.y += f.y;
            f = h2_to_f2(v2.z); a2.x += f.x; a2.y += f.y;
            f = h2_to_f2(v2.w); a3.x += f.x; a3.y += f.y;
            f = h2_to_f2(v3.x); a0.x += f.x; a0.y += f.y;
            f = h2_to_f2(v3.y); a1.x += f.x; a1.y += f.y;
            f = h2_to_f2(v3.z); a2.x += f.x; a2.y += f.y;
            f = h2_to_f2(v3.w); a3.x += f.x; a3.y += f.y;
        }
        for (; j < e; j++) {
            int n = g_csr[j];
            uint4 v = __ldcg(&T[n * 8 + sub]);
            float2 f;
            f = h2_to_f2(v.x); a0.x += f.x; a0.y += f.y;
            f = h2_to_f2(v.y); a1.x += f.x; a1.y += f.y;
            f = h2_to_f2(v.z); a2.x += f.x; a2.y += f.y;
            f = h2_to_f2(v.w); a3.x += f.x; a3.y += f.y;
        }
    }

    float4 acc0 = make_float4(a0.x, a0.y, a1.x, a1.y);
    float4 acc1 = make_float4(a2.x, a2.y, a3.x, a3.y);

    float4 h0, h1;
    {
        float4 bb = ((const float4*)b)[sub * 2 + 0];
        float4 gm = ((const float4*)gamma)[sub * 2 + 0];
        float4 bt = ((const float4*)beta)[sub * 2 + 0];
        float4 mn = ((const float4*)mean)[sub * 2 + 0];
        float4 vr = ((const float4*)var)[sub * 2 + 0];
        h0.x = fmaxf(0.f, (acc0.x * dv + bb.x - mn.x) * rsqrtf(vr.x + BN_EPS) * gm.x + bt.x);
        h0.y = fmaxf(0.f, (acc0.y * dv + bb.y - mn.y) * rsqrtf(vr.y + BN_EPS) * gm.y + bt.y);
        h0.z = fmaxf(0.f, (acc0.z * dv + bb.z - mn.z) * rsqrtf(vr.z + BN_EPS) * gm.z + bt.z);
        h0.w = fmaxf(0.f, (acc0.w * dv + bb.w - mn.w) * rsqrtf(vr.w + BN_EPS) * gm.w + bt.w);
    }
    {
        float4 bb = ((const float4*)b)[sub * 2 + 1];
        float4 gm = ((const float4*)gamma)[sub * 2 + 1];
        float4 bt = ((const float4*)beta)[sub * 2 + 1];
        float4 mn = ((const float4*)mean)[sub * 2 + 1];
        float4 vr = ((const float4*)var)[sub * 2 + 1];
        h1.x = fmaxf(0.f, (acc1.x * dv + bb.x - mn.x) * rsqrtf(vr.x + BN_EPS) * gm.x + bt.x);
        h1.y = fmaxf(0.f, (acc1.y * dv + bb.y - mn.y) * rsqrtf(vr.y + BN_EPS) * gm.y + bt.y);
        h1.z = fmaxf(0.f, (acc1.z * dv + bb.z - mn.z) * rsqrtf(vr.z + BN_EPS) * gm.z + bt.z);
        h1.w = fmaxf(0.f, (acc1.w * dv + bb.w - mn.w) * rsqrtf(vr.w + BN_EPS) * gm.w + bt.w);
    }

    if (!last) {
        ((float4*)g_h)[node * 16 + sub * 2 + 0] = h0;
        ((float4*)g_h)[node * 16 + sub * 2 + 1] = h1;
    } else {
        float4 w0 = ((const float4*)lin_w)[sub * 2 + 0];
        float4 w1 = ((const float4*)lin_w)[sub * 2 + 1];
        float dot = h0.x * w0.x + h0.y * w0.y + h0.z * w0.z + h0.w * w0.w
                  + h1.x * w1.x + h1.y * w1.y + h1.z * w1.z + h1.w * w1.w;
        #pragma unroll
        for (int o = 4; o; o >>= 1)
            dot += __shfl_down_sync(0xFFFFFFFFu, dot, o, 8);
        if (sub == 0) out[node] = dot + lin_b[0];
    }
}

// ---------------------------------------------------------------------------
extern "C" void kernel_launch(void* const* d_in, const int* in_sizes, int n_in,
                              void* d_out, int out_size) {
    const float* x        = (const float*)d_in[0];
    const int*   ei       = (const int*)  d_in[1];   // [2, E]
    const float* Ws       = (const float*)d_in[2];   // [3, 64, 64]
    const float* bs       = (const float*)d_in[3];
    const float* gammas   = (const float*)d_in[4];
    const float* betas    = (const float*)d_in[5];
    const float* means    = (const float*)d_in[6];
    const float* variances= (const float*)d_in[7];
    const float* lin_w    = (const float*)d_in[8];
    const float* lin_b    = (const float*)d_in[9];

    const int* rowi = ei;
    const int* coli = ei + N_EDGES;

    const int agg_blocks = (N_NODES * 8 + 255) / 256;

    // K1: hist + unscaled layer-0 GEMM (overlap verified in R8)
    k1_hist_gemm0<<<HIST_BLOCKS + GEMM_TILES, 256>>>(coli, x, Ws);
    scan1_kernel<<<NB1, 256>>>();
    scan3_kernel<<<(N_NODES + 255) / 256, 256>>>();
    fill_kernel<<<(N_EDGES / 4 + 255) / 256, 256>>>(rowi, coli);

    for (int l = 0; l < 3; l++) {
        if (l > 0)
            gemm_kernel<<<GEMM_TILES, 256>>>(Ws + l * D * D);
        aggregate_kernel<<<agg_blocks, 256>>>(bs + l * D, gammas + l * D,
                                              betas + l * D, means + l * D,
                                              variances + l * D,
                                              lin_w, lin_b, (float*)d_out,
                                              (l == 2) ? 1 : 0,
                                              (l == 0) ? 1 : 0);
    }
}

// round 13
// speedup vs baseline: 1.4582x; 1.0436x over previous
#include <cuda_runtime.h>
#include <cuda_fp16.h>
#include <cuda_bf16.h>

#define N_NODES 50000
#define N_EDGES 800000
#define D 64
#define BN_EPS 1e-5f

#define SCAN_BS 1024
#define NB1 ((N_NODES + SCAN_BS - 1) / SCAN_BS)   // 49

#define FILL_BLOCKS 782    // ceil(200000/256)
#define GEMM_TILES 391     // ceil(50000/128)

// Scratch (device globals; no allocations allowed).
// INVARIANT: g_cnt is all-zero at kernel_launch entry (zero-init at load;
// scan1_kernel re-zeroes it after use within every call).
__device__ uint2  g_t16[N_NODES * 16];     // t' = (h@W)*dinv, fp16 (64 halves/row)
__device__ float4 g_h[N_NODES * (D/4)];    // layer output (fp32)
__device__ float  g_dinv[N_NODES];
__device__ int    g_cnt[N_NODES];
__device__ int    g_off[N_NODES + 1];
__device__ int    g_blk[NB1];
__device__ unsigned short g_rank[N_EDGES]; // edge rank within target node
__device__ unsigned short g_csr[N_EDGES];  // source node per CSR slot (fits u16)

__device__ __forceinline__ float2 h2_to_f2(unsigned u) {
    __half2 h = *reinterpret_cast<__half2*>(&u);
    return __half22float2(h);
}
__device__ __forceinline__ unsigned smem_u32(const void* p) {
    return (unsigned)__cvta_generic_to_shared(p);
}

// ---------------------------------------------------------------------------
// hist: in-degree histogram; atomicAdd return value IS the edge's rank
// within its target node -> store it, making the CSR fill atomic-free.
// ---------------------------------------------------------------------------
__global__ void hist_kernel(const int* __restrict__ coli) {
    int idx = blockIdx.x * blockDim.x + threadIdx.x;   // int4 index
    if (idx < N_EDGES / 4) {
        int4 c = ((const int4*)coli)[idx];
        int r0 = atomicAdd(&g_cnt[c.x], 1);
        int r1 = atomicAdd(&g_cnt[c.y], 1);
        int r2 = atomicAdd(&g_cnt[c.z], 1);
        int r3 = atomicAdd(&g_cnt[c.w], 1);
        ushort4 rk;
        rk.x = (unsigned short)r0;
        rk.y = (unsigned short)r1;
        rk.z = (unsigned short)r2;
        rk.w = (unsigned short)r3;
        ((ushort4*)g_rank)[idx] = rk;
    }
}

// ---------------------------------------------------------------------------
// scan1: block partials + local offsets; also dinv and cnt re-zero.
// ---------------------------------------------------------------------------
__global__ __launch_bounds__(256) void scan1_kernel() {
    __shared__ int sh[8];
    int tid = threadIdx.x;
    int lane = tid & 31;
    int wid = tid >> 5;
    int base = blockIdx.x * SCAN_BS + tid * 4;

    int c[4];
    #pragma unroll
    for (int i = 0; i < 4; i++)
        c[i] = (base + i < N_NODES) ? g_cnt[base + i] : 0;
    int tot = c[0] + c[1] + c[2] + c[3];

    int v = tot;
    #pragma unroll
    for (int o = 1; o < 32; o <<= 1) {
        int n = __shfl_up_sync(0xFFFFFFFFu, v, o);
        if (lane >= o) v += n;
    }
    if (lane == 31) sh[wid] = v;
    __syncthreads();
    if (tid < 8) {
        int w = sh[tid];
        #pragma unroll
        for (int o = 1; o < 8; o <<= 1) {
            int n = __shfl_up_sync(0xFFu, w, o, 8);
            if (tid >= o) w += n;
        }
        sh[tid] = w;
    }
    __syncthreads();
    int incl = v + ((wid > 0) ? sh[wid - 1] : 0);
    int run = incl - tot;
    if (tid == 255) g_blk[blockIdx.x] = incl;
    #pragma unroll
    for (int i = 0; i < 4; i++) {
        if (base + i < N_NODES) {
            g_off[base + i] = run;
            g_dinv[base + i] = rsqrtf((float)(c[i] + 1));   // +1 self loop
            g_cnt[base + i] = 0;                            // restore invariant
        }
        run += c[i];
    }
}

// scan3: add cross-block prefix to offsets.
__global__ __launch_bounds__(256) void scan3_kernel() {
    __shared__ int pref;
    int tid = threadIdx.x;
    if (tid == 0) pref = 0;
    __syncthreads();
    int chunk = (blockIdx.x * 256) >> 10;
    if (tid < chunk) atomicAdd(&pref, g_blk[tid]);   // chunk <= 48 < 256
    __syncthreads();

    int i = blockIdx.x * 256 + tid;
    if (i < N_NODES) {
        g_off[i] = g_off[i] + pref;
        if (i == 0) g_off[N_NODES] = N_EDGES;
    }
}

// ---------------------------------------------------------------------------
// GEMM tile body (HMMA): t' = (in @ W) * dinv, fp16 out to g_t16.
// 128-node tile, 256 threads; warp = 16 rows x 64 cols, mma.m16n8k16.
// ---------------------------------------------------------------------------
#define APAD 72

__device__ __forceinline__ void gemm_tile(int bid, const float* in,
                                          const float* W) {
    __shared__ __half sA[128 * APAD];
    __shared__ __half sB[64 * APAD];

    int tid = threadIdx.x;
    int node0 = bid * 128;

    #pragma unroll
    for (int i = 0; i < 8; i++) {
        int g = tid + 256 * i;
        int k = g >> 5;
        int n2 = g & 31;
        float2 w = ((const float2*)W)[k * 32 + n2];
        *(__half2*)&sB[k * APAD + n2 * 2] = __floats2half2_rn(w.x, w.y);
    }
    #pragma unroll
    for (int i = 0; i < 8; i++) {
        int g = tid + 256 * i;
        int r = g >> 4;
        int c4 = g & 15;
        int node = node0 + r;
        float4 v = make_float4(0.f, 0.f, 0.f, 0.f);
        if (node < N_NODES) {
            if (in) v = ((const float4*)in)[node * 16 + c4];
            else    v = ((const float4*)g_h)[node * 16 + c4];
        }
        __half2* dst = (__half2*)&sA[r * APAD + c4 * 4];
        dst[0] = __floats2half2_rn(v.x, v.y);
        dst[1] = __floats2half2_rn(v.z, v.w);
    }
    __syncthreads();

    int warp = tid >> 5;
    int lane = tid & 31;

    float acc[8][4];
    #pragma unroll
    for (int nc = 0; nc < 8; nc++)
        #pragma unroll
        for (int i = 0; i < 4; i++) acc[nc][i] = 0.f;

    #pragma unroll
    for (int kc = 0; kc < 4; kc++) {
        unsigned a0, a1, a2, a3;
        {
            unsigned addr = smem_u32(
                &sA[(warp * 16 + (lane & 15)) * APAD + kc * 16 + (lane >> 4) * 8]);
            asm volatile("ldmatrix.sync.aligned.m8n8.x4.shared.b16 {%0,%1,%2,%3}, [%4];"
                         : "=r"(a0), "=r"(a1), "=r"(a2), "=r"(a3) : "r"(addr));
        }
        #pragma unroll
        for (int nc = 0; nc < 8; nc++) {
            unsigned b0, b1;
            unsigned addr = smem_u32(&sB[(kc * 16 + (lane & 15)) * APAD + nc * 8]);
            asm volatile("ldmatrix.sync.aligned.m8n8.x2.trans.shared.b16 {%0,%1}, [%2];"
                         : "=r"(b0), "=r"(b1) : "r"(addr));
            asm volatile(
                "mma.sync.aligned.m16n8k16.row.col.f32.f16.f16.f32 "
                "{%0,%1,%2,%3}, {%4,%5,%6,%7}, {%8,%9}, {%0,%1,%2,%3};"
                : "+f"(acc[nc][0]), "+f"(acc[nc][1]), "+f"(acc[nc][2]), "+f"(acc[nc][3])
                : "r"(a0), "r"(a1), "r"(a2), "r"(a3), "r"(b0), "r"(b1));
        }
    }

    int r0 = warp * 16 + (lane >> 2);
    int c0 = lane & 3;
    int node_a = node0 + r0;
    int node_b = node0 + r0 + 8;
    float dva = (node_a < N_NODES) ? g_dinv[node_a] : 0.f;
    float dvb = (node_b < N_NODES) ? g_dinv[node_b] : 0.f;
    __half2* T2 = (__half2*)g_t16;

    #pragma unroll
    for (int nc = 0; nc < 8; nc++) {
        int h2i = nc * 4 + c0;
        if (node_a < N_NODES)
            T2[node_a * 32 + h2i] = __floats2half2_rn(acc[nc][0] * dva, acc[nc][1] * dva);
        if (node_b < N_NODES)
            T2[node_b * 32 + h2i] = __floats2half2_rn(acc[nc][2] * dvb, acc[nc][3] * dvb);
    }
}

// ---------------------------------------------------------------------------
// K4 (fat): atomic-free CSR fill (blocks [0, FILL_BLOCKS)) + scaled gemm0.
// Both parts are short; fill is streaming, gemm0 is tensor-bound.
// ---------------------------------------------------------------------------
__global__ __launch_bounds__(256) void k4_fill_gemm0(const int* __restrict__ rowi,
                                                     const int* __restrict__ coli,
                                                     const float* __restrict__ x,
                                                     const float* __restrict__ W0) {
    if (blockIdx.x < FILL_BLOCKS) {
        int idx = blockIdx.x * 256 + threadIdx.x;
        if (idx < N_EDGES / 4) {
            int4 r = ((const int4*)rowi)[idx];
            int4 c = ((const int4*)coli)[idx];
            ushort4 rk = ((const ushort4*)g_rank)[idx];
            g_csr[g_off[c.x] + rk.x] = (unsigned short)r.x;
            g_csr[g_off[c.y] + rk.y] = (unsigned short)r.y;
            g_csr[g_off[c.z] + rk.z] = (unsigned short)r.z;
            g_csr[g_off[c.w] + rk.w] = (unsigned short)r.w;
        }
    } else {
        gemm_tile(blockIdx.x - FILL_BLOCKS, x, W0);
    }
}

// ---------------------------------------------------------------------------
// Standalone GEMM (layers 1,2).
// ---------------------------------------------------------------------------
__global__ __launch_bounds__(256) void gemm_kernel(const float* __restrict__ W) {
    gemm_tile(blockIdx.x, nullptr, W);
}

// ---------------------------------------------------------------------------
// Aggregate (pull-mode, fp16 gather via L2, fp32 accumulate) + fused BN/ReLU
// (+ final linear head when last).  8 threads per node, 8 feats each (16B).
// ---------------------------------------------------------------------------
__global__ __launch_bounds__(256) void aggregate_kernel(
        const float* __restrict__ b,
        const float* __restrict__ gamma,
        const float* __restrict__ beta,
        const float* __restrict__ mean,
        const float* __restrict__ var,
        const float* __restrict__ lin_w,
        const float* __restrict__ lin_b,
        float* __restrict__ out,
        int last) {
    int t = blockIdx.x * blockDim.x + threadIdx.x;
    int node = t >> 3;
    int sub = t & 7;
    if (node >= N_NODES) return;

    const uint4* T = (const uint4*)g_t16;

    int s = g_off[node];
    int e = g_off[node + 1];

    float2 a0, a1, a2, a3;
    {
        uint4 v = __ldcg(&T[node * 8 + sub]);
        a0 = h2_to_f2(v.x); a1 = h2_to_f2(v.y);
        a2 = h2_to_f2(v.z); a3 = h2_to_f2(v.w);
    }

    int j = s;
    for (; j + 4 <= e; j += 4) {
        int n0 = g_csr[j + 0];
        int n1 = g_csr[j + 1];
        int n2 = g_csr[j + 2];
        int n3 = g_csr[j + 3];
        uint4 v0 = __ldcg(&T[n0 * 8 + sub]);
        uint4 v1 = __ldcg(&T[n1 * 8 + sub]);
        uint4 v2 = __ldcg(&T[n2 * 8 + sub]);
        uint4 v3 = __ldcg(&T[n3 * 8 + sub]);
        float2 f;
        f = h2_to_f2(v0.x); a0.x += f.x; a0.y += f.y;
        f = h2_to_f2(v0.y); a1.x += f.x; a1.y += f.y;
        f = h2_to_f2(v0.z); a2.x += f.x; a2.y += f.y;
        f = h2_to_f2(v0.w); a3.x += f.x; a3.y += f.y;
        f = h2_to_f2(v1.x); a0.x += f.x; a0.y += f.y;
        f = h2_to_f2(v1.y); a1.x += f.x; a1.y += f.y;
        f = h2_to_f2(v1.z); a2.x += f.x; a2.y += f.y;
        f = h2_to_f2(v1.w); a3.x += f.x; a3.y += f.y;
        f = h2_to_f2(v2.x); a0.x += f.x; a0.y += f.y;
        f = h2_to_f2(v2.y); a1.x += f.x; a1.y += f.y;
        f = h2_to_f2(v2.z); a2.x += f.x; a2.y += f.y;
        f = h2_to_f2(v2.w); a3.x += f.x; a3.y += f.y;
        f = h2_to_f2(v3.x); a0.x += f.x; a0.y += f.y;
        f = h2_to_f2(v3.y); a1.x += f.x; a1.y += f.y;
        f = h2_to_f2(v3.z); a2.x += f.x; a2.y += f.y;
        f = h2_to_f2(v3.w); a3.x += f.x; a3.y += f.y;
    }
    for (; j < e; j++) {
        int n = g_csr[j];
        uint4 v = __ldcg(&T[n * 8 + sub]);
        float2 f;
        f = h2_to_f2(v.x); a0.x += f.x; a0.y += f.y;
        f = h2_to_f2(v.y); a1.x += f.x; a1.y += f.y;
        f = h2_to_f2(v.z); a2.x += f.x; a2.y += f.y;
        f = h2_to_f2(v.w); a3.x += f.x; a3.y += f.y;
    }

    float dv = g_dinv[node];
    float4 acc0 = make_float4(a0.x, a0.y, a1.x, a1.y);
    float4 acc1 = make_float4(a2.x, a2.y, a3.x, a3.y);

    float4 h0, h1;
    {
        float4 bb = ((const float4*)b)[sub * 2 + 0];
        float4 gm = ((const float4*)gamma)[sub * 2 + 0];
        float4 bt = ((const float4*)beta)[sub * 2 + 0];
        float4 mn = ((const float4*)mean)[sub * 2 + 0];
        float4 vr = ((const float4*)var)[sub * 2 + 0];
        h0.x = fmaxf(0.f, (acc0.x * dv + bb.x - mn.x) * rsqrtf(vr.x + BN_EPS) * gm.x + bt.x);
        h0.y = fmaxf(0.f, (acc0.y * dv + bb.y - mn.y) * rsqrtf(vr.y + BN_EPS) * gm.y + bt.y);
        h0.z = fmaxf(0.f, (acc0.z * dv + bb.z - mn.z) * rsqrtf(vr.z + BN_EPS) * gm.z + bt.z);
        h0.w = fmaxf(0.f, (acc0.w * dv + bb.w - mn.w) * rsqrtf(vr.w + BN_EPS) * gm.w + bt.w);
    }
    {
        float4 bb = ((const float4*)b)[sub * 2 + 1];
        float4 gm = ((const float4*)gamma)[sub * 2 + 1];
        float4 bt = ((const float4*)beta)[sub * 2 + 1];
        float4 mn = ((const float4*)mean)[sub * 2 + 1];
        float4 vr = ((const float4*)var)[sub * 2 + 1];
        h1.x = fmaxf(0.f, (acc1.x * dv + bb.x - mn.x) * rsqrtf(vr.x + BN_EPS) * gm.x + bt.x);
        h1.y = fmaxf(0.f, (acc1.y * dv + bb.y - mn.y) * rsqrtf(vr.y + BN_EPS) * gm.y + bt.y);
        h1.z = fmaxf(0.f, (acc1.z * dv + bb.z - mn.z) * rsqrtf(vr.z + BN_EPS) * gm.z + bt.z);
        h1.w = fmaxf(0.f, (acc1.w * dv + bb.w - mn.w) * rsqrtf(vr.w + BN_EPS) * gm.w + bt.w);
    }

    if (!last) {
        ((float4*)g_h)[node * 16 + sub * 2 + 0] = h0;
        ((float4*)g_h)[node * 16 + sub * 2 + 1] = h1;
    } else {
        float4 w0 = ((const float4*)lin_w)[sub * 2 + 0];
        float4 w1 = ((const float4*)lin_w)[sub * 2 + 1];
        float dot = h0.x * w0.x + h0.y * w0.y + h0.z * w0.z + h0.w * w0.w
                  + h1.x * w1.x + h1.y * w1.y + h1.z * w1.z + h1.w * w1.w;
        #pragma unroll
        for (int o = 4; o; o >>= 1)
            dot += __shfl_down_sync(0xFFFFFFFFu, dot, o, 8);
        if (sub == 0) out[node] = dot + lin_b[0];
    }
}

// ---------------------------------------------------------------------------
extern "C" void kernel_launch(void* const* d_in, const int* in_sizes, int n_in,
                              void* d_out, int out_size) {
    const float* x        = (const float*)d_in[0];
    const int*   ei       = (const int*)  d_in[1];   // [2, E]
    const float* Ws       = (const float*)d_in[2];   // [3, 64, 64]
    const float* bs       = (const float*)d_in[3];
    const float* gammas   = (const float*)d_in[4];
    const float* betas    = (const float*)d_in[5];
    const float* means    = (const float*)d_in[6];
    const float* variances= (const float*)d_in[7];
    const float* lin_w    = (const float*)d_in[8];
    const float* lin_b    = (const float*)d_in[9];

    const int* rowi = ei;
    const int* coli = ei + N_EDGES;

    const int agg_blocks = (N_NODES * 8 + 255) / 256;

    hist_kernel<<<(N_EDGES / 4 + 255) / 256, 256>>>(coli);
    scan1_kernel<<<NB1, 256>>>();
    scan3_kernel<<<(N_NODES + 255) / 256, 256>>>();
    // K4: atomic-free CSR fill + scaled layer-0 GEMM
    k4_fill_gemm0<<<FILL_BLOCKS + GEMM_TILES, 256>>>(rowi, coli, x, Ws);

    for (int l = 0; l < 3; l++) {
        if (l > 0)
            gemm_kernel<<<GEMM_TILES, 256>>>(Ws + l * D * D);
        aggregate_kernel<<<agg_blocks, 256>>>(bs + l * D, gammas + l * D,
                                              betas + l * D, means + l * D,
                                              variances + l * D,
                                              lin_w, lin_b, (float*)d_out,
                                              (l == 2) ? 1 : 0);
    }
}